// round 2
// baseline (speedup 1.0000x reference)
#include <cuda_runtime.h>
#include <cuda_bf16.h>
#include <math.h>

// ---------------- problem constants ----------------
#define SEQ    128
#define BATCH  64
#define EMB    512
#define HID    1024
#define G4     4096           // 4*HID
#define VOCAB  32000
#define M1     8192           // SEQ*BATCH

// ---------------- device scratch (no runtime alloc allowed) ----------------
__device__ float g_xg[33554432];     // [8192][4096] input-side gate pre-activations (+bias)
__device__ float g_hseq[8388608];    // [128][64][1024] hidden sequence
__device__ float g_part[1048576];    // [4][64][4096] K-split partial gate GEMM
__device__ float g_h[2][65536];      // ping-pong h state [64][1024]
__device__ float g_c[65536];         // c state [64][1024]

// ---------------- init: copy h0/c0 into state buffers ----------------
__global__ void init_state(const float* __restrict__ h0, const float* __restrict__ c0) {
    int gid = blockIdx.x * blockDim.x + threadIdx.x;
    if (gid < 65536) {
        g_h[0][gid] = h0[gid];
        g_c[gid]    = c0[gid];
    }
}

// ---------------- Phase A: xg = emb[input] @ W_ih + b_lstm ----------------
// M=8192 (gathered rows), N=4096, K=512. 128x128 tile, BK=16, 256 thr, 8x8 micro.
__global__ __launch_bounds__(256) void embed_gemm(
    const int* __restrict__ inp, const float* __restrict__ emb,
    const float* __restrict__ Wih, const float* __restrict__ bl)
{
    __shared__ float As[16][132];
    __shared__ float Bs[16][132];
    __shared__ int rowidx[128];

    int t  = threadIdx.x;
    int m0 = blockIdx.y * 128;
    int n0 = blockIdx.x * 128;
    int ty = t >> 4, tx = t & 15;

    if (t < 128) rowidx[t] = inp[m0 + t];
    __syncthreads();

    float acc[8][8];
    #pragma unroll
    for (int i = 0; i < 8; i++)
        #pragma unroll
        for (int j = 0; j < 8; j++) acc[i][j] = 0.f;

    for (int k0 = 0; k0 < EMB; k0 += 16) {
        // A tile: 128 rows x 16 k, gathered via embedding indices
        #pragma unroll
        for (int i = 0; i < 2; i++) {
            int idx = t + i * 256;              // 512 float4
            int m = idx >> 2, q = idx & 3;
            float4 v = *(const float4*)(emb + (size_t)rowidx[m] * EMB + k0 + q * 4);
            As[q*4+0][m] = v.x; As[q*4+1][m] = v.y;
            As[q*4+2][m] = v.z; As[q*4+3][m] = v.w;
        }
        // B tile: 16 k x 128 n from W_ih (row-major K x 4096)
        #pragma unroll
        for (int i = 0; i < 2; i++) {
            int idx = t + i * 256;              // 512 float4
            int k = idx >> 5, c4 = idx & 31;
            *(float4*)&Bs[k][c4*4] = *(const float4*)(Wih + (size_t)(k0+k) * G4 + n0 + c4*4);
        }
        __syncthreads();
        #pragma unroll
        for (int kk = 0; kk < 16; kk++) {
            float a[8], b[8];
            *(float4*)(a)   = *(float4*)&As[kk][ty*8];
            *(float4*)(a+4) = *(float4*)&As[kk][ty*8+4];
            *(float4*)(b)   = *(float4*)&Bs[kk][tx*8];
            *(float4*)(b+4) = *(float4*)&Bs[kk][tx*8+4];
            #pragma unroll
            for (int i = 0; i < 8; i++)
                #pragma unroll
                for (int j = 0; j < 8; j++) acc[i][j] += a[i] * b[j];
        }
        __syncthreads();
    }

    #pragma unroll
    for (int i = 0; i < 8; i++) {
        int m = m0 + ty*8 + i;
        #pragma unroll
        for (int j = 0; j < 8; j++) {
            int n = n0 + tx*8 + j;
            g_xg[(size_t)m * G4 + n] = acc[i][j] + bl[n];
        }
    }
}

// ---------------- Phase B1: per-step gate GEMM partials ----------------
// gates_part[kc] = h @ W_hh[kc-slice]. Tile: 64 batch x 128 gate-cols
// (32 hid units x 4 gates), K-chunk 256. grid (32, 4), 128 threads, 8x8 micro.
__global__ __launch_bounds__(128) void step_gemm(const float* __restrict__ Whh, int s)
{
    __shared__ float Hs[16][68];
    __shared__ float Ws[16][132];

    int t  = threadIdx.x;
    int j0 = blockIdx.x * 32;       // hid-unit base for this tile
    int kbase = blockIdx.y * 256;   // K chunk
    const float* h = g_h[s & 1];
    int ty = t >> 4, tx = t & 15;   // ty 0..7 (8 batch rows each), tx 0..15 (8 cols each)

    float acc[8][8];
    #pragma unroll
    for (int i = 0; i < 8; i++)
        #pragma unroll
        for (int j = 0; j < 8; j++) acc[i][j] = 0.f;

    for (int k0 = kbase; k0 < kbase + 256; k0 += 16) {
        // A tile: 64 b x 16 k = 256 float4
        #pragma unroll
        for (int i = 0; i < 2; i++) {
            int idx = t + i * 128;
            int b = idx >> 2, q = idx & 3;
            float4 v = *(const float4*)(h + b * HID + k0 + q * 4);
            Hs[q*4+0][b] = v.x; Hs[q*4+1][b] = v.y;
            Hs[q*4+2][b] = v.z; Hs[q*4+3][b] = v.w;
        }
        // B tile: 16 k x 128 c, c -> gate col (q*1024 + j0 + u)
        #pragma unroll
        for (int i = 0; i < 4; i++) {
            int idx = t + i * 128;              // 512 float4
            int k = idx >> 5, c4 = idx & 31;
            int c = c4 * 4;
            int qg = c >> 5, u = c & 31;
            *(float4*)&Ws[k][c] =
                *(const float4*)(Whh + (size_t)(k0+k) * G4 + qg * HID + j0 + u);
        }
        __syncthreads();
        #pragma unroll
        for (int kk = 0; kk < 16; kk++) {
            float a[8], b[8];
            *(float4*)(a)   = *(float4*)&Hs[kk][ty*8];
            *(float4*)(a+4) = *(float4*)&Hs[kk][ty*8+4];
            *(float4*)(b)   = *(float4*)&Ws[kk][tx*8];
            *(float4*)(b+4) = *(float4*)&Ws[kk][tx*8+4];
            #pragma unroll
            for (int i = 0; i < 8; i++)
                #pragma unroll
                for (int j = 0; j < 8; j++) acc[i][j] += a[i] * b[j];
        }
        __syncthreads();
    }

    float* P = g_part + (size_t)blockIdx.y * BATCH * G4;
    #pragma unroll
    for (int i = 0; i < 8; i++) {
        int b = ty*8 + i;
        #pragma unroll
        for (int j = 0; j < 8; j++) {
            int c = tx*8 + j;
            int qg = c >> 5, u = c & 31;
            P[(size_t)b * G4 + qg * HID + j0 + u] = acc[i][j];
        }
    }
}

// ---------------- Phase B2: LSTM cell (reduce partials + activations) ----------------
__global__ __launch_bounds__(256) void lstm_cell(int s)
{
    int gid = blockIdx.x * blockDim.x + threadIdx.x;   // 0..65535
    int b = gid >> 10, j = gid & 1023;
    const float* xg = g_xg + (size_t)s * BATCH * G4 + (size_t)b * G4;

    float gi = xg[j], gf = xg[HID + j], gg = xg[2*HID + j], go = xg[3*HID + j];
    #pragma unroll
    for (int kc = 0; kc < 4; kc++) {
        const float* P = g_part + (size_t)kc * BATCH * G4 + (size_t)b * G4;
        gi += P[j]; gf += P[HID + j]; gg += P[2*HID + j]; go += P[3*HID + j];
    }
    float iv = 1.f / (1.f + expf(-gi));
    float fv = 1.f / (1.f + expf(-gf));
    float gv = tanhf(gg);
    float ov = 1.f / (1.f + expf(-go));
    float cv = fv * g_c[gid] + iv * gv;
    g_c[gid] = cv;
    float hv = ov * tanhf(cv);
    g_h[(s + 1) & 1][gid] = hv;
    g_hseq[(size_t)s * 65536 + gid] = hv;
}

// ---------------- Phase C: logits = hseq_flat @ lin_W^T + lin_b ----------------
// M=8192, N=32000, K=1024. B is [N][K] row-major (K-contiguous). 128x128 tile.
__global__ __launch_bounds__(256) void out_gemm(
    const float* __restrict__ linW, const float* __restrict__ linb,
    float* __restrict__ out)
{
    __shared__ float As[16][132];
    __shared__ float Bs[16][132];

    int t  = threadIdx.x;
    int m0 = blockIdx.y * 128;
    int n0 = blockIdx.x * 128;
    int ty = t >> 4, tx = t & 15;

    float acc[8][8];
    #pragma unroll
    for (int i = 0; i < 8; i++)
        #pragma unroll
        for (int j = 0; j < 8; j++) acc[i][j] = 0.f;

    for (int k0 = 0; k0 < HID; k0 += 16) {
        // A tile from hidden_seq flat (8192 x 1024, row-major)
        #pragma unroll
        for (int i = 0; i < 2; i++) {
            int idx = t + i * 256;
            int m = idx >> 2, q = idx & 3;
            float4 v = *(const float4*)(g_hseq + (size_t)(m0+m) * HID + k0 + q * 4);
            As[q*4+0][m] = v.x; As[q*4+1][m] = v.y;
            As[q*4+2][m] = v.z; As[q*4+3][m] = v.w;
        }
        // B tile: lin_W rows n0..n0+127, k contiguous -> transpose into Bs[k][n]
        #pragma unroll
        for (int i = 0; i < 2; i++) {
            int idx = t + i * 256;
            int n = idx >> 2, q = idx & 3;
            float4 v = *(const float4*)(linW + (size_t)(n0+n) * HID + k0 + q * 4);
            Bs[q*4+0][n] = v.x; Bs[q*4+1][n] = v.y;
            Bs[q*4+2][n] = v.z; Bs[q*4+3][n] = v.w;
        }
        __syncthreads();
        #pragma unroll
        for (int kk = 0; kk < 16; kk++) {
            float a[8], b[8];
            *(float4*)(a)   = *(float4*)&As[kk][ty*8];
            *(float4*)(a+4) = *(float4*)&As[kk][ty*8+4];
            *(float4*)(b)   = *(float4*)&Bs[kk][tx*8];
            *(float4*)(b+4) = *(float4*)&Bs[kk][tx*8+4];
            #pragma unroll
            for (int i = 0; i < 8; i++)
                #pragma unroll
                for (int j = 0; j < 8; j++) acc[i][j] += a[i] * b[j];
        }
        __syncthreads();
    }

    #pragma unroll
    for (int i = 0; i < 8; i++) {
        int m = m0 + ty*8 + i;
        #pragma unroll
        for (int j = 0; j < 8; j++) {
            int n = n0 + tx*8 + j;
            out[(size_t)m * VOCAB + n] = acc[i][j] + linb[n];
        }
    }
}

// ---------------- tail: write final (h_t, c_t) ----------------
__global__ void write_state(float* __restrict__ out_h, float* __restrict__ out_c)
{
    int gid = blockIdx.x * blockDim.x + threadIdx.x;
    if (gid < 65536) {
        out_h[gid] = g_h[0][gid];   // after 128 steps, state lives in buffer 0
        out_c[gid] = g_c[gid];
    }
}

// ---------------- launch ----------------
extern "C" void kernel_launch(void* const* d_in, const int* in_sizes, int n_in,
                              void* d_out, int out_size)
{
    const int*   inp  = (const int*)  d_in[0];
    const float* emb  = (const float*)d_in[1];
    const float* Wih  = (const float*)d_in[2];
    const float* Whh  = (const float*)d_in[3];
    const float* bl   = (const float*)d_in[4];
    const float* linW = (const float*)d_in[5];
    const float* linb = (const float*)d_in[6];
    const float* h0   = (const float*)d_in[7];
    const float* c0   = (const float*)d_in[8];
    float* out = (float*)d_out;

    init_state<<<256, 256>>>(h0, c0);
    embed_gemm<<<dim3(32, 64), 256>>>(inp, emb, Wih, bl);

    for (int s = 0; s < SEQ; s++) {
        step_gemm<<<dim3(32, 4), 128>>>(Whh, s);
        lstm_cell<<<256, 256>>>(s);
    }

    out_gemm<<<dim3(250, 64), 256>>>(linW, linb, out);

    // output layout: [logits (8192*32000)][h_t (65536)][c_t (65536)]
    float* out_h = out + ((size_t)out_size - 131072);
    float* out_c = out + ((size_t)out_size - 65536);
    write_state<<<256, 256>>>(out_h, out_c);
}

// round 5
// speedup vs baseline: 1.9075x; 1.9075x over previous
#include <cuda_runtime.h>
#include <cuda_bf16.h>
#include <math.h>
#include <stdint.h>

// ---------------- problem constants ----------------
#define SEQ    128
#define BATCH  64
#define EMB    512
#define HID    1024
#define G4     4096           // 4*HID
#define VOCAB  32000
#define M1     8192           // SEQ*BATCH

// ---------------- device scratch (no runtime alloc allowed) ----------------
__device__ float g_xg[33554432];          // [8192][4096] input-side gate preacts (+bias)
__device__ float g_part[2097152];         // [8][64][4096] K-split partial gate GEMM
__device__ float g_h[2][65536];           // ping-pong h state [64][1024]
__device__ float g_c[65536];              // c state
__device__ __nv_bfloat16 g_hseq_hi[8388608];  // [8192][1024] hidden seq, bf16 hi
__device__ __nv_bfloat16 g_hseq_lo[8388608];  // bf16 lo residual
__device__ __nv_bfloat16 g_wh[32768000];      // lin_W bf16 hi  [32000][1024]
__device__ __nv_bfloat16 g_wl[32768000];      // lin_W bf16 lo

// ---------------- PTX helpers (base ISA only: sm_80-compatible) ----------------
__device__ __forceinline__ uint32_t smem_u32(const void* p) {
    uint32_t a;
    asm("{ .reg .u64 t; cvta.to.shared.u64 t, %1; cvt.u32.u64 %0, t; }" : "=r"(a) : "l"(p));
    return a;
}
__device__ __forceinline__ void cp16(uint32_t s, const void* g) {
    asm volatile("{ .reg .u64 gp; cvta.to.global.u64 gp, %1; "
                 "cp.async.cg.shared.global [%0], [gp], 16; }"
                 :: "r"(s), "l"(g) : "memory");
}
#define CP_COMMIT() asm volatile("cp.async.commit_group;" ::: "memory")
#define CP_WAIT(n)  asm volatile("cp.async.wait_group %0;" :: "n"(n) : "memory")

__device__ __forceinline__ void ldsm4(uint32_t* r, uint32_t a) {
    asm volatile("ldmatrix.sync.aligned.m8n8.x4.shared.b16 {%0,%1,%2,%3}, [%4];"
                 : "=r"(r[0]), "=r"(r[1]), "=r"(r[2]), "=r"(r[3]) : "r"(a));
}
__device__ __forceinline__ void mma16816(float* d, const uint32_t* a, uint32_t b0, uint32_t b1) {
    asm volatile("mma.sync.aligned.m16n8k16.row.col.f32.bf16.bf16.f32 "
                 "{%0,%1,%2,%3}, {%4,%5,%6,%7}, {%8,%9}, {%0,%1,%2,%3};"
                 : "+f"(d[0]), "+f"(d[1]), "+f"(d[2]), "+f"(d[3])
                 : "r"(a[0]), "r"(a[1]), "r"(a[2]), "r"(a[3]), "r"(b0), "r"(b1));
}

__device__ __forceinline__ uint32_t bfpack(float a, float b) {
    __nv_bfloat162 p = __floats2bfloat162_rn(a, b);
    return *reinterpret_cast<uint32_t*>(&p);
}

// ---------------- init: copy h0/c0 into state buffers ----------------
__global__ void init_state(const float* __restrict__ h0, const float* __restrict__ c0) {
    int gid = blockIdx.x * blockDim.x + threadIdx.x;
    if (gid < 65536) {
        g_h[0][gid] = h0[gid];
        g_c[gid]    = c0[gid];
    }
}

// ---------------- convert lin_W to bf16 hi/lo ----------------
__global__ __launch_bounds__(256) void conv_w(const float* __restrict__ W) {
    size_t i = (size_t)blockIdx.x * 256 + threadIdx.x;   // float4 index, 8.192M total
    float4 v = ((const float4*)W)[i];
    float a[4] = {v.x, v.y, v.z, v.w};
    float hi[4], lo[4];
    #pragma unroll
    for (int j = 0; j < 4; j++) {
        __nv_bfloat16 h = __float2bfloat16(a[j]);
        hi[j] = __bfloat162float(h);
        lo[j] = a[j] - hi[j];
    }
    uint2 uh, ul;
    uh.x = bfpack(hi[0], hi[1]); uh.y = bfpack(hi[2], hi[3]);
    ul.x = bfpack(lo[0], lo[1]); ul.y = bfpack(lo[2], lo[3]);
    ((uint2*)g_wh)[i] = uh;
    ((uint2*)g_wl)[i] = ul;
}

// ---------------- Phase A: xg = emb[input] @ W_ih + b_lstm ----------------
__global__ __launch_bounds__(256) void embed_gemm(
    const int* __restrict__ inp, const float* __restrict__ emb,
    const float* __restrict__ Wih, const float* __restrict__ bl)
{
    __shared__ float As[16][132];
    __shared__ float Bs[16][132];
    __shared__ int rowidx[128];

    int t  = threadIdx.x;
    int m0 = blockIdx.y * 128;
    int n0 = blockIdx.x * 128;
    int ty = t >> 4, tx = t & 15;

    if (t < 128) rowidx[t] = inp[m0 + t];
    __syncthreads();

    float acc[8][8];
    #pragma unroll
    for (int i = 0; i < 8; i++)
        #pragma unroll
        for (int j = 0; j < 8; j++) acc[i][j] = 0.f;

    for (int k0 = 0; k0 < EMB; k0 += 16) {
        #pragma unroll
        for (int i = 0; i < 2; i++) {
            int idx = t + i * 256;
            int m = idx >> 2, q = idx & 3;
            float4 v = *(const float4*)(emb + (size_t)rowidx[m] * EMB + k0 + q * 4);
            As[q*4+0][m] = v.x; As[q*4+1][m] = v.y;
            As[q*4+2][m] = v.z; As[q*4+3][m] = v.w;
        }
        #pragma unroll
        for (int i = 0; i < 2; i++) {
            int idx = t + i * 256;
            int k = idx >> 5, c4 = idx & 31;
            *(float4*)&Bs[k][c4*4] = *(const float4*)(Wih + (size_t)(k0+k) * G4 + n0 + c4*4);
        }
        __syncthreads();
        #pragma unroll
        for (int kk = 0; kk < 16; kk++) {
            float a[8], b[8];
            *(float4*)(a)   = *(float4*)&As[kk][ty*8];
            *(float4*)(a+4) = *(float4*)&As[kk][ty*8+4];
            *(float4*)(b)   = *(float4*)&Bs[kk][tx*8];
            *(float4*)(b+4) = *(float4*)&Bs[kk][tx*8+4];
            #pragma unroll
            for (int i = 0; i < 8; i++)
                #pragma unroll
                for (int j = 0; j < 8; j++) acc[i][j] += a[i] * b[j];
        }
        __syncthreads();
    }

    #pragma unroll
    for (int i = 0; i < 8; i++) {
        int m = m0 + ty*8 + i;
        #pragma unroll
        for (int j = 0; j < 8; j++) {
            int n = n0 + tx*8 + j;
            g_xg[(size_t)m * G4 + n] = acc[i][j] + bl[n];
        }
    }
}

// ---------------- Phase B1: per-step gate GEMM partials (K-split 8) ----------------
__global__ __launch_bounds__(128) void step_gemm(const float* __restrict__ Whh, int s)
{
    __shared__ float Hs[16][68];
    __shared__ float Ws[16][132];

    int t  = threadIdx.x;
    int j0 = blockIdx.x * 32;
    int kbase = blockIdx.y * 128;
    const float* h = g_h[s & 1];
    int ty = t >> 4, tx = t & 15;

    float acc[8][8];
    #pragma unroll
    for (int i = 0; i < 8; i++)
        #pragma unroll
        for (int j = 0; j < 8; j++) acc[i][j] = 0.f;

    for (int k0 = kbase; k0 < kbase + 128; k0 += 16) {
        #pragma unroll
        for (int i = 0; i < 2; i++) {
            int idx = t + i * 128;
            int b = idx >> 2, q = idx & 3;
            float4 v = *(const float4*)(h + b * HID + k0 + q * 4);
            Hs[q*4+0][b] = v.x; Hs[q*4+1][b] = v.y;
            Hs[q*4+2][b] = v.z; Hs[q*4+3][b] = v.w;
        }
        #pragma unroll
        for (int i = 0; i < 4; i++) {
            int idx = t + i * 128;
            int k = idx >> 5, c4 = idx & 31;
            int c = c4 * 4;
            int qg = c >> 5, u = c & 31;
            *(float4*)&Ws[k][c] =
                *(const float4*)(Whh + (size_t)(k0+k) * G4 + qg * HID + j0 + u);
        }
        __syncthreads();
        #pragma unroll
        for (int kk = 0; kk < 16; kk++) {
            float a[8], b[8];
            *(float4*)(a)   = *(float4*)&Hs[kk][ty*8];
            *(float4*)(a+4) = *(float4*)&Hs[kk][ty*8+4];
            *(float4*)(b)   = *(float4*)&Ws[kk][tx*8];
            *(float4*)(b+4) = *(float4*)&Ws[kk][tx*8+4];
            #pragma unroll
            for (int i = 0; i < 8; i++)
                #pragma unroll
                for (int j = 0; j < 8; j++) acc[i][j] += a[i] * b[j];
        }
        __syncthreads();
    }

    float* P = g_part + (size_t)blockIdx.y * BATCH * G4;
    #pragma unroll
    for (int i = 0; i < 8; i++) {
        int b = ty*8 + i;
        #pragma unroll
        for (int j = 0; j < 8; j++) {
            int c = tx*8 + j;
            int qg = c >> 5, u = c & 31;
            P[(size_t)b * G4 + qg * HID + j0 + u] = acc[i][j];
        }
    }
}

// ---------------- Phase B2: LSTM cell ----------------
__global__ __launch_bounds__(256) void lstm_cell(int s)
{
    int gid = blockIdx.x * blockDim.x + threadIdx.x;   // 0..65535
    int b = gid >> 10, j = gid & 1023;
    const float* xg = g_xg + (size_t)s * BATCH * G4 + (size_t)b * G4;

    float gi = xg[j], gf = xg[HID + j], gg = xg[2*HID + j], go = xg[3*HID + j];
    #pragma unroll
    for (int kc = 0; kc < 8; kc++) {
        const float* P = g_part + (size_t)kc * BATCH * G4 + (size_t)b * G4;
        gi += P[j]; gf += P[HID + j]; gg += P[2*HID + j]; go += P[3*HID + j];
    }
    float iv = 1.f / (1.f + expf(-gi));
    float fv = 1.f / (1.f + expf(-gf));
    float gv = tanhf(gg);
    float ov = 1.f / (1.f + expf(-go));
    float cv = fv * g_c[gid] + iv * gv;
    g_c[gid] = cv;
    float hv = ov * tanhf(cv);
    g_h[(s + 1) & 1][gid] = hv;

    size_t idx = (size_t)s * 65536 + gid;
    __nv_bfloat16 hh = __float2bfloat16(hv);
    g_hseq_hi[idx] = hh;
    g_hseq_lo[idx] = __float2bfloat16(hv - __bfloat162float(hh));
}

// ---------------- Phase C: HMMA bf16-split GEMM (mma.sync, base PTX) ----------------
// logits[8192,32000] = hseq @ linW^T + linb.
// CTA tile 128x128, BK=32, double-buffered cp.async, 8 warps (2x4), warp 64x32.
// 3-term split: hi*hi + hi*lo + lo*hi.
// B is [n][k] row-major in smem -> NON-trans ldmatrix gives the mma B fragment
// (n = lane/4, k = 2*(lane%4)) directly. (.trans was the R4 bug.)
#define ROWB   80                            // padded row stride in bytes (32 bf16 + 8 pad)
#define STG    (4 * 128 * ROWB)              // 40960 bytes per stage (Ah, Al, Bh, Bl)
#define TCSM   (2 * STG)                     // 81920

__global__ __launch_bounds__(256) void out_gemm_mma(
    const float* __restrict__ linb, float* __restrict__ out)
{
    extern __shared__ char smem[];
    uint32_t sb = smem_u32(smem);
    int t = threadIdx.x, wid = t >> 5, lane = t & 31;
    int m0 = blockIdx.x * 128;               // m fastest -> B tiles L2-resident
    int n0 = blockIdx.y * 128;

    int wm = (wid >> 2) * 64;
    int wn = (wid & 3) * 32;

    float acc[4][4][4];
    #pragma unroll
    for (int i = 0; i < 4; i++)
        #pragma unroll
        for (int j = 0; j < 4; j++)
            #pragma unroll
            for (int q = 0; q < 4; q++) acc[i][j][q] = 0.f;

    // load chunk indices for this thread (2 row-chunks per array)
    int r0 = t >> 2, c0 = t & 3;             // rows 0..63
    int r1 = r0 + 64;

    // ---- prologue: stage 0 ----
    {
        const int k0 = 0;
        uint32_t s0 = sb;
        #pragma unroll
        for (int p = 0; p < 2; p++) {
            int r = p ? r1 : r0;
            uint32_t so = s0 + (uint32_t)r * ROWB + c0 * 16;
            size_t ga = (size_t)(m0 + r) * HID + k0 + c0 * 8;
            size_t gb = (size_t)(n0 + r) * HID + k0 + c0 * 8;
            cp16(so,                  g_hseq_hi + ga);
            cp16(so + 1 * 128 * ROWB, g_hseq_lo + ga);
            cp16(so + 2 * 128 * ROWB, g_wh + gb);
            cp16(so + 3 * 128 * ROWB, g_wl + gb);
        }
        CP_COMMIT();
    }

    for (int ch = 0; ch < 32; ch++) {
        int buf = ch & 1;
        // prefetch next stage
        if (ch + 1 < 32) {
            const int k0 = (ch + 1) * 32;
            uint32_t s0 = sb + (buf ^ 1) * STG;
            #pragma unroll
            for (int p = 0; p < 2; p++) {
                int r = p ? r1 : r0;
                uint32_t so = s0 + (uint32_t)r * ROWB + c0 * 16;
                size_t ga = (size_t)(m0 + r) * HID + k0 + c0 * 8;
                size_t gb = (size_t)(n0 + r) * HID + k0 + c0 * 8;
                cp16(so,                  g_hseq_hi + ga);
                cp16(so + 1 * 128 * ROWB, g_hseq_lo + ga);
                cp16(so + 2 * 128 * ROWB, g_wh + gb);
                cp16(so + 3 * 128 * ROWB, g_wl + gb);
            }
            CP_COMMIT();
            CP_WAIT(1);
        } else {
            CP_WAIT(0);
        }
        __syncthreads();

        uint32_t sA = sb + buf * STG;
        uint32_t sB = sA + 2 * 128 * ROWB;

        #pragma unroll
        for (int kh = 0; kh < 2; kh++) {
            uint32_t ah[4][4], al[4][4], bh[2][4], bl[2][4];
            // A frags (hi & lo), 16x16 tiles
            #pragma unroll
            for (int mi = 0; mi < 4; mi++) {
                uint32_t addr = sA + (uint32_t)(wm + mi * 16 + (lane & 15)) * ROWB
                              + (kh * 16 + ((lane >> 4) * 8)) * 2;
                ldsm4(ah[mi], addr);
                ldsm4(al[mi], addr + 128 * ROWB);
            }
            // B frags (hi & lo): [n][k] row-major tiles, NON-trans ldmatrix
            #pragma unroll
            for (int ng = 0; ng < 2; ng++) {
                int row = wn + ng * 16 + ((lane >> 4) & 1) * 8 + (lane & 7);
                uint32_t addr = sB + (uint32_t)row * ROWB
                              + kh * 32 + ((lane >> 3) & 1) * 16;
                ldsm4(bh[ng], addr);
                ldsm4(bl[ng], addr + 128 * ROWB);
            }
            // 48 mma: hi*hi + hi*lo + lo*hi
            #pragma unroll
            for (int mi = 0; mi < 4; mi++) {
                #pragma unroll
                for (int ni = 0; ni < 4; ni++) {
                    int ix = ni >> 1, g = ni & 1;
                    uint32_t bh0 = bh[ix][g*2], bh1 = bh[ix][g*2+1];
                    uint32_t bl0 = bl[ix][g*2], bl1 = bl[ix][g*2+1];
                    mma16816(acc[mi][ni], ah[mi], bh0, bh1);
                    mma16816(acc[mi][ni], ah[mi], bl0, bl1);
                    mma16816(acc[mi][ni], al[mi], bh0, bh1);
                }
            }
        }
        __syncthreads();
    }

    // ---- epilogue ----
    #pragma unroll
    for (int mi = 0; mi < 4; mi++) {
        int row = m0 + wm + mi * 16 + (lane >> 2);
        #pragma unroll
        for (int ni = 0; ni < 4; ni++) {
            int col = n0 + wn + ni * 8 + (lane & 3) * 2;
            float b0 = linb[col], b1 = linb[col + 1];
            float2 v0 = make_float2(acc[mi][ni][0] + b0, acc[mi][ni][1] + b1);
            float2 v1 = make_float2(acc[mi][ni][2] + b0, acc[mi][ni][3] + b1);
            *(float2*)(out + (size_t)row * VOCAB + col) = v0;
            *(float2*)(out + (size_t)(row + 8) * VOCAB + col) = v1;
        }
    }
}

// ---------------- tail: write final (h_t, c_t) ----------------
__global__ void write_state(float* __restrict__ out_h, float* __restrict__ out_c)
{
    int gid = blockIdx.x * blockDim.x + threadIdx.x;
    if (gid < 65536) {
        out_h[gid] = g_h[0][gid];
        out_c[gid] = g_c[gid];
    }
}

// ---------------- launch ----------------
extern "C" void kernel_launch(void* const* d_in, const int* in_sizes, int n_in,
                              void* d_out, int out_size)
{
    const int*   inp  = (const int*)  d_in[0];
    const float* emb  = (const float*)d_in[1];
    const float* Wih  = (const float*)d_in[2];
    const float* Whh  = (const float*)d_in[3];
    const float* bl   = (const float*)d_in[4];
    const float* linW = (const float*)d_in[5];
    const float* linb = (const float*)d_in[6];
    const float* h0   = (const float*)d_in[7];
    const float* c0   = (const float*)d_in[8];
    float* out = (float*)d_out;

    cudaFuncSetAttribute(out_gemm_mma, cudaFuncAttributeMaxDynamicSharedMemorySize, TCSM);

    init_state<<<256, 256>>>(h0, c0);
    conv_w<<<32000, 256>>>(linW);
    embed_gemm<<<dim3(32, 64), 256>>>(inp, emb, Wih, bl);

    for (int s = 0; s < SEQ; s++) {
        step_gemm<<<dim3(32, 8), 128>>>(Whh, s);
        lstm_cell<<<256, 256>>>(s);
    }

    out_gemm_mma<<<dim3(64, 250), 256, TCSM>>>(linb, out);

    float* out_h = out + ((size_t)out_size - 131072);
    float* out_c = out + ((size_t)out_size - 65536);
    write_state<<<256, 256>>>(out_h, out_c);
}